// round 5
// baseline (speedup 1.0000x reference)
#include <cuda_runtime.h>
#include <cstdint>

#define NN 8192
#define NF 512
#define NH 256
#define FALPHA 0.5f

// ==================== scratch ====================
__device__ float g_rowsum[NN];
__device__ float g_colsum[NN];
__device__ float g_drow[NN];
__device__ float g_dcol[NN];
__device__ float g_adjF[(size_t)NN * NN];  // rna(adj), fragment-major
__device__ float g_xF[NN * NF];            // rna(x), fragment-major
__device__ float g_W1r[NF * NH];           // rna(W1), canonical [K][N]
__device__ float g_XW1[NN * NH];
__device__ float g_Bs1[NN * NH];           // rna(dcol ⊙ XW1), canonical [K][N]
__device__ float g_T1[NN * NH];
__device__ float g_Bs2[NN * NH];           // rna(dcol ⊙ T1), canonical [K][N]
__device__ float g_T2[NN * NH];
__device__ float g_G[NN * 2];
__device__ float g_S1[NN * 2];
__device__ float g_S2[NN * 2];

// ==================== helpers ====================
__device__ __forceinline__ unsigned f2tf(float f) {
    unsigned r;
    asm("cvt.rna.tf32.f32 %0, %1;" : "=r"(r) : "f"(f));
    return r;
}
__device__ __forceinline__ float rnaf(float f) { return __uint_as_float(f2tf(f)); }

__device__ __forceinline__ void cp16(void* smem, const void* gmem) {
    unsigned s = (unsigned)__cvta_generic_to_shared(smem);
    asm volatile("cp.async.cg.shared.global [%0], [%1], 16;\n" :: "r"(s), "l"(gmem));
}

// ==================== fused: degrees + fragment-major rounded adj ========
__global__ void k_zero() {
    int i = blockIdx.x * blockDim.x + threadIdx.x;
    if (i < NN) { g_rowsum[i] = 0.f; g_colsum[i] = 0.f; }
}

// grid (64, 8): block = 128 rows x 1024 cols. One adj read; writes g_adjF
// (fragment-major: tile (16m x 8k) -> 32 float4, lane l = g*4+t holds
// {A[m0+g][k0+t], A[m0+g+8][k0+t], A[m0+g][k0+t+4], A[m0+g+8][k0+t+4]}).
__global__ __launch_bounds__(256) void k_prep(const float* __restrict__ adj) {
    __shared__ float srow[128];
    __shared__ float scol[1024];
    int tid = threadIdx.x, w = tid >> 5, l = tid & 31, g = l >> 2, t = l & 3;
    int I = blockIdx.x, Jy = blockIdx.y;
    if (tid < 128) srow[tid] = 0.f;
    for (int i = tid; i < 1024; i += 256) scol[i] = 0.f;
    __syncthreads();

    int m0 = I * 128 + w * 16;
    float rs_lo = 0.f, rs_hi = 0.f;
    float4* dst = (float4*)g_adjF;
#pragma unroll 4
    for (int kc = 0; kc < 128; kc++) {
        int k0 = Jy * 1024 + kc * 8;
        const float* p = adj + (size_t)(m0 + g) * NN + k0 + t;
        float a0 = p[0], a2 = p[4];
        const float* q = p + (size_t)8 * NN;
        float a1 = q[0], a3 = q[4];

        rs_lo += a0 + a2;
        rs_hi += a1 + a3;
        float c0 = a0 + a1, c1 = a2 + a3;
#pragma unroll
        for (int mk = 4; mk <= 16; mk <<= 1) {
            c0 += __shfl_xor_sync(0xffffffffu, c0, mk);
            c1 += __shfl_xor_sync(0xffffffffu, c1, mk);
        }
        if (g == 0) {
            atomicAdd(&scol[kc * 8 + t], c0);
            atomicAdd(&scol[kc * 8 + t + 4], c1);
        }
        int jl = kc >> 2, ks = kc & 3;
        size_t tile = ((size_t)(I * 256 + Jy * 32 + jl)) * 32 + w * 4 + ks;
        dst[tile * 32 + l] = make_float4(rnaf(a0), rnaf(a1), rnaf(a2), rnaf(a3));
    }
    atomicAdd(&srow[w * 16 + g], rs_lo);
    atomicAdd(&srow[w * 16 + g + 8], rs_hi);
    __syncthreads();
    if (tid < 128) atomicAdd(&g_rowsum[I * 128 + tid], srow[tid]);
    for (int i = tid; i < 1024; i += 256) atomicAdd(&g_colsum[Jy * 1024 + i], scol[i]);
}

__global__ void k_finalize() {
    int i = blockIdx.x * blockDim.x + threadIdx.x;
    if (i >= NN) return;
    float rs = g_rowsum[i];
    g_drow[i] = rs > 0.f ? rsqrtf(rs) : 0.f;
    float cs = g_colsum[i];
    g_dcol[i] = cs > 0.f ? rsqrtf(cs) : 0.f;
}

// x -> fragment-major rounded (K = 512)
__global__ __launch_bounds__(256) void k_fragX(const float* __restrict__ x) {
    int tid = threadIdx.x, w = tid >> 5, l = tid & 31, g = l >> 2, t = l & 3;
    int I = blockIdx.x;
    int m0 = I * 128 + w * 16;
    float4* dst = (float4*)g_xF;
#pragma unroll 4
    for (int kc = 0; kc < 64; kc++) {
        int k0 = kc * 8;
        const float* p = x + (size_t)(m0 + g) * NF + k0 + t;
        float a0 = p[0], a2 = p[4];
        const float* q = p + 8 * NF;
        float a1 = q[0], a3 = q[4];
        size_t tile = ((size_t)(I * 16 + (kc >> 2))) * 32 + w * 4 + (kc & 3);
        dst[tile * 32 + l] = make_float4(rnaf(a0), rnaf(a1), rnaf(a2), rnaf(a3));
    }
}

__global__ void k_roundW1(const float* __restrict__ W1) {
    int i = blockIdx.x * blockDim.x + threadIdx.x;
    if (i < NF * NH) g_W1r[i] = rnaf(W1[i]);
}

// ==================== tf32 mma.sync GEMM, fragment-major A ====================
// C[128 x 128 tile] = [drow ⊙] (A @ B), A fragment-major with KT32 k-chunks/row-tile,
// B canonical [K][NH] pre-rounded. AUX: Aux[m][n] = rna(dcol[m]*C[m][n]).
#define SBF 136
#define ASTG 4096            // floats per A stage (16KB)
#define BSTG (32 * SBF)      // floats per B stage (17408B)
#define SMEM_MM ((3 * ASTG + 3 * BSTG) * 4)

__global__ __launch_bounds__(256) void k_mma2(const float* __restrict__ AF,
                                              const float* __restrict__ Bc,
                                              float* __restrict__ C,
                                              float* __restrict__ Aux,
                                              int KT, int SCALE, int AUX) {
    extern __shared__ float sm[];
    float* As = sm;
    float* Bs = sm + 3 * ASTG;

    const int tid = threadIdx.x;
    const int wid = tid >> 5, lane = tid & 31;
    const int g = lane >> 2, t = lane & 3;
    const int wmI = (wid & 1) * 4;        // A fragment-tile base (mt index)
    const int wn  = (wid >> 1) * 32;
    const int bm = blockIdx.y * 128, bn = blockIdx.x * 128;

    float acc[4][4][4];
#pragma unroll
    for (int i = 0; i < 4; i++)
#pragma unroll
        for (int j = 0; j < 4; j++)
#pragma unroll
            for (int r = 0; r < 4; r++) acc[i][j][r] = 0.f;

    const float4* Abase = (const float4*)AF + (size_t)blockIdx.y * KT * 1024;

#define LOADSTAGE(kt, s) do {                                                  \
    const float4* Asrc = Abase + (size_t)(kt) * 1024;                          \
    float* ad = As + (s) * ASTG;                                               \
    float* bd = Bs + (s) * BSTG;                                               \
    _Pragma("unroll")                                                          \
    for (int i = 0; i < 4; i++) {                                              \
        int ch = tid + i * 256;                                                \
        cp16(ad + ch * 4, Asrc + ch);                                          \
        int r = ch >> 5, c = ch & 31;                                          \
        cp16(bd + r * SBF + c * 4, Bc + (size_t)((kt) * 32 + r) * NH + bn + c * 4); \
    }                                                                          \
    asm volatile("cp.async.commit_group;\n");                                  \
} while (0)

    LOADSTAGE(0, 0);
    LOADSTAGE(1, 1);

    for (int kt = 0; kt < KT; kt++) {
        if (kt == KT - 1) asm volatile("cp.async.wait_group 0;\n");
        else              asm volatile("cp.async.wait_group 1;\n");
        __syncthreads();

        int buf = kt % 3;
        const float* as = As + buf * ASTG;
        const float* bs = Bs + buf * BSTG;

#pragma unroll
        for (int ks = 0; ks < 4; ks++) {
            float4 af[4];
#pragma unroll
            for (int mt = 0; mt < 4; mt++)
                af[mt] = *(const float4*)(as + ((wmI + mt) * 4 + ks) * 128 + lane * 4);
            unsigned bf[4][2];
#pragma unroll
            for (int nt = 0; nt < 4; nt++) {
                const float* bp = bs + (ks * 8 + t) * SBF + wn + nt * 8 + g;
                bf[nt][0] = __float_as_uint(bp[0]);
                bf[nt][1] = __float_as_uint(bp[4 * SBF]);
            }
#pragma unroll
            for (int mt = 0; mt < 4; mt++)
#pragma unroll
                for (int nt = 0; nt < 4; nt++) {
                    asm volatile(
                        "mma.sync.aligned.m16n8k8.row.col.f32.tf32.tf32.f32 "
                        "{%0,%1,%2,%3}, {%4,%5,%6,%7}, {%8,%9}, {%0,%1,%2,%3};\n"
                        : "+f"(acc[mt][nt][0]), "+f"(acc[mt][nt][1]),
                          "+f"(acc[mt][nt][2]), "+f"(acc[mt][nt][3])
                        : "r"(__float_as_uint(af[mt].x)), "r"(__float_as_uint(af[mt].y)),
                          "r"(__float_as_uint(af[mt].z)), "r"(__float_as_uint(af[mt].w)),
                          "r"(bf[nt][0]), "r"(bf[nt][1]));
                }
        }
        if (kt + 2 < KT) LOADSTAGE(kt + 2, (kt + 2) % 3);
    }

    // epilogue
#pragma unroll
    for (int mt = 0; mt < 4; mt++) {
        int r0 = bm + (wmI + mt) * 16 + g;
        int r1 = r0 + 8;
        float s0 = SCALE ? g_drow[r0] : 1.f;
        float s1 = SCALE ? g_drow[r1] : 1.f;
        float d0 = g_dcol[r0], d1 = g_dcol[r1];
#pragma unroll
        for (int nt = 0; nt < 4; nt++) {
            int c = bn + wn + nt * 8 + 2 * t;
            float v0 = acc[mt][nt][0] * s0, v1 = acc[mt][nt][1] * s0;
            float v2 = acc[mt][nt][2] * s1, v3 = acc[mt][nt][3] * s1;
            *(float2*)(C + (size_t)r0 * NH + c) = make_float2(v0, v1);
            *(float2*)(C + (size_t)r1 * NH + c) = make_float2(v2, v3);
            if (AUX) {
                *(float2*)(Aux + (size_t)r0 * NH + c) =
                    make_float2(rnaf(d0 * v0), rnaf(d0 * v1));
                *(float2*)(Aux + (size_t)r1 * NH + c) =
                    make_float2(rnaf(d1 * v2), rnaf(d1 * v3));
            }
        }
    }
}

// ==================== fused hidden + output-gemm ====================
__global__ void k_hidden(const float* __restrict__ W2) {
    int row  = blockIdx.x * 8 + (threadIdx.x >> 5);
    int lane = threadIdx.x & 31;
    float g0 = 0.f, g1 = 0.f;
    const float* xw = g_XW1 + (size_t)row * NH;
    const float* t1 = g_T1 + (size_t)row * NH;
    const float* t2 = g_T2 + (size_t)row * NH;
#pragma unroll
    for (int j = lane; j < NH; j += 32) {
        float p = FALPHA * xw[j] + (FALPHA - 1.f) * t1[j] - t2[j];
        float h = fmaxf(p, 0.f);
        g0 = fmaf(h, __ldg(&W2[j * 2 + 0]), g0);
        g1 = fmaf(h, __ldg(&W2[j * 2 + 1]), g1);
    }
#pragma unroll
    for (int o = 16; o; o >>= 1) {
        g0 += __shfl_xor_sync(0xffffffffu, g0, o);
        g1 += __shfl_xor_sync(0xffffffffu, g1, o);
    }
    if (!lane) {
        g_G[row * 2 + 0] = g0;
        g_G[row * 2 + 1] = g1;
    }
}

// ==================== narrow DAD apply (N=2), exact fp32 ====================
__global__ void k_narrow(const float* __restrict__ adj,
                         const float* __restrict__ Bsrc,
                         float* __restrict__ Sdst) {
    extern __shared__ float2 sB[];
    int tid = threadIdx.x;
    for (int k = tid; k < NN; k += 256) {
        float sc = g_dcol[k];
        sB[k] = make_float2(sc * Bsrc[k * 2], sc * Bsrc[k * 2 + 1]);
    }
    __syncthreads();

    int row  = blockIdx.x * 8 + (tid >> 5);
    int lane = tid & 31;
    const float4* a = (const float4*)(adj + (size_t)row * NN);
    float s0 = 0.f, s1 = 0.f;
#pragma unroll 4
    for (int it = lane; it < NN / 4; it += 32) {
        float4 v = a[it];
        int k = it * 4;
        float2 b0 = sB[k], b1 = sB[k + 1], b2 = sB[k + 2], b3 = sB[k + 3];
        s0 += v.x * b0.x + v.y * b1.x + v.z * b2.x + v.w * b3.x;
        s1 += v.x * b0.y + v.y * b1.y + v.z * b2.y + v.w * b3.y;
    }
#pragma unroll
    for (int o = 16; o; o >>= 1) {
        s0 += __shfl_xor_sync(0xffffffffu, s0, o);
        s1 += __shfl_xor_sync(0xffffffffu, s1, o);
    }
    if (!lane) {
        float sc = g_drow[row];
        Sdst[row * 2 + 0] = sc * s0;
        Sdst[row * 2 + 1] = sc * s1;
    }
}

// ==================== final log-softmax ====================
__global__ void k_final(const float* __restrict__ b2, float* __restrict__ out) {
    int i = blockIdx.x * blockDim.x + threadIdx.x;
    if (i >= NN) return;
    float o0 = FALPHA * g_G[i * 2 + 0] + (FALPHA - 1.f) * g_S1[i * 2 + 0] - g_S2[i * 2 + 0] + b2[0];
    float o1 = FALPHA * g_G[i * 2 + 1] + (FALPHA - 1.f) * g_S1[i * 2 + 1] - g_S2[i * 2 + 1] + b2[1];
    float m = fmaxf(o0, o1);
    float lse = m + logf(expf(o0 - m) + expf(o1 - m));
    out[i * 2 + 0] = o0 - lse;
    out[i * 2 + 1] = o1 - lse;
}

// ==================== launch ====================
extern "C" void kernel_launch(void* const* d_in, const int* in_sizes, int n_in,
                              void* d_out, int out_size) {
    const float* x   = (const float*)d_in[0];
    const float* adj = (const float*)d_in[1];
    const float* W1  = (const float*)d_in[2];
    const float* W2  = (const float*)d_in[3];
    const float* b2  = (const float*)d_in[4];
    float* out = (float*)d_out;
    (void)in_sizes; (void)n_in; (void)out_size;

    float *pAdjF, *pXF, *pW1r, *pXW1, *pBs1, *pT1, *pBs2, *pT2, *pG, *pS1, *pS2;
    cudaGetSymbolAddress((void**)&pAdjF, g_adjF);
    cudaGetSymbolAddress((void**)&pXF, g_xF);
    cudaGetSymbolAddress((void**)&pW1r, g_W1r);
    cudaGetSymbolAddress((void**)&pXW1, g_XW1);
    cudaGetSymbolAddress((void**)&pBs1, g_Bs1);
    cudaGetSymbolAddress((void**)&pT1, g_T1);
    cudaGetSymbolAddress((void**)&pBs2, g_Bs2);
    cudaGetSymbolAddress((void**)&pT2, g_T2);
    cudaGetSymbolAddress((void**)&pG, g_G);
    cudaGetSymbolAddress((void**)&pS1, g_S1);
    cudaGetSymbolAddress((void**)&pS2, g_S2);

    cudaFuncSetAttribute(k_mma2, cudaFuncAttributeMaxDynamicSharedMemorySize, SMEM_MM);
    cudaFuncSetAttribute(k_narrow, cudaFuncAttributeMaxDynamicSharedMemorySize, 65536);

    // degrees + rounded fragment-major adj in ONE adj pass
    k_zero<<<NN / 256, 256>>>();
    k_prep<<<dim3(64, 8), 256>>>(adj);
    k_finalize<<<NN / 256, 256>>>();

    // pre-rounded operands
    k_fragX<<<64, 256>>>(x);
    k_roundW1<<<(NF * NH) / 256, 256>>>(W1);

    // XW1 = x @ W1 ; aux Bs1 = rna(dcol ⊙ XW1)
    k_mma2<<<dim3(2, 64), 256, SMEM_MM>>>(pXF, pW1r, pXW1, pBs1, NF / 32, 0, 1);

    // T1 = drow ⊙ (adj @ Bs1) ; aux Bs2 = rna(dcol ⊙ T1)
    k_mma2<<<dim3(2, 64), 256, SMEM_MM>>>(pAdjF, pBs1, pT1, pBs2, NN / 32, 1, 1);

    // T2 = drow ⊙ (adj @ Bs2)
    k_mma2<<<dim3(2, 64), 256, SMEM_MM>>>(pAdjF, pBs2, pT2, (float*)0, NN / 32, 1, 0);

    // H = relu(adj_f @ XW1), G = H @ W2
    k_hidden<<<NN / 8, 256>>>(W2);

    // S1 = DAD @ G ; S2 = DAD @ S1
    k_narrow<<<NN / 8, 256, 65536>>>(adj, pG, pS1);
    k_narrow<<<NN / 8, 256, 65536>>>(adj, pS1, pS2);

    k_final<<<NN / 256, 256>>>(b2, out);
}

// round 6
// speedup vs baseline: 1.4724x; 1.4724x over previous
#include <cuda_runtime.h>
#include <cuda_fp16.h>
#include <cstdint>

#define NN 8192
#define NF 512
#define NH 256
#define FALPHA 0.5f

// ==================== scratch ====================
__device__ float g_rowsum[NN];
__device__ float g_colsum[NN];
__device__ float g_drow[NN];
__device__ float g_dcol[NN];
__device__ __half g_adjh[(size_t)NN * NN];  // rn(adj), row-major fp16
__device__ __half g_xh[NN * NF];            // rn(x), row-major
__device__ __half g_W1h[NH * NF];           // rn(W1)^T  [n][k]
__device__ __half g_Bs1h[(size_t)NH * NN];  // rn(dcol ⊙ XW1)^T [n][m]
__device__ __half g_Bs2h[(size_t)NH * NN];  // rn(dcol ⊙ T1)^T  [n][m]
__device__ float g_XW1[NN * NH];
__device__ float g_T1[NN * NH];
__device__ float g_T2[NN * NH];
__device__ float g_G[NN * 2];
__device__ float g_S1[NN * 2];
__device__ float g_S2[NN * 2];

// ==================== helpers ====================
__device__ __forceinline__ void cp16(void* smem, const void* gmem) {
    unsigned s = (unsigned)__cvta_generic_to_shared(smem);
    asm volatile("cp.async.cg.shared.global [%0], [%1], 16;\n" :: "r"(s), "l"(gmem));
}

// ==================== prep: degrees + fp16 adj in one pass ====================
__global__ void k_zero() {
    int i = blockIdx.x * blockDim.x + threadIdx.x;
    if (i < NN) g_colsum[i] = 0.f;
}

// grid 128 blocks x 64 rows. Coalesced read of adj; writes g_adjh; row/col sums.
__global__ __launch_bounds__(256) void k_prep(const float* __restrict__ adj) {
    __shared__ float srow[64];
    int tid = threadIdx.x, lane = tid & 31;
    int r0 = blockIdx.x * 64;
    if (tid < 64) srow[tid] = 0.f;
    __syncthreads();

    float4 colacc[8];
#pragma unroll
    for (int j = 0; j < 8; j++) colacc[j] = make_float4(0.f, 0.f, 0.f, 0.f);

    for (int r = 0; r < 64; r++) {
        int row = r0 + r;
        const float4* src = (const float4*)(adj + (size_t)row * NN);
        uint2* dst = (uint2*)(g_adjh + (size_t)row * NN);
        float rs = 0.f;
#pragma unroll
        for (int j = 0; j < 8; j++) {
            int c4 = tid + j * 256;
            float4 v = src[c4];
            colacc[j].x += v.x; colacc[j].y += v.y;
            colacc[j].z += v.z; colacc[j].w += v.w;
            rs += (v.x + v.y) + (v.z + v.w);
            __half2 h01 = __floats2half2_rn(v.x, v.y);
            __half2 h23 = __floats2half2_rn(v.z, v.w);
            uint2 pk;
            pk.x = *(unsigned*)&h01;
            pk.y = *(unsigned*)&h23;
            dst[c4] = pk;
        }
#pragma unroll
        for (int o = 16; o; o >>= 1) rs += __shfl_xor_sync(0xffffffffu, rs, o);
        if (!lane) atomicAdd(&srow[r], rs);
    }
    __syncthreads();
    if (tid < 64) g_rowsum[r0 + tid] = srow[tid];
#pragma unroll
    for (int j = 0; j < 8; j++) {
        int c = (tid + j * 256) * 4;
        atomicAdd(&g_colsum[c + 0], colacc[j].x);
        atomicAdd(&g_colsum[c + 1], colacc[j].y);
        atomicAdd(&g_colsum[c + 2], colacc[j].z);
        atomicAdd(&g_colsum[c + 3], colacc[j].w);
    }
}

__global__ void k_finalize() {
    int i = blockIdx.x * blockDim.x + threadIdx.x;
    if (i >= NN) return;
    float rs = g_rowsum[i];
    g_drow[i] = rs > 0.f ? rsqrtf(rs) : 0.f;
    float cs = g_colsum[i];
    g_dcol[i] = cs > 0.f ? rsqrtf(cs) : 0.f;
}

__global__ void k_halfx(const float* __restrict__ x) {
    int i = blockIdx.x * blockDim.x + threadIdx.x;
    if (i < NN * NF) g_xh[i] = __float2half_rn(x[i]);
}

__global__ void k_halfW1(const float* __restrict__ W1) {
    int i = blockIdx.x * blockDim.x + threadIdx.x;
    if (i >= NF * NH) return;
    int k = i / NH, n = i % NH;
    g_W1h[n * NF + k] = __float2half_rn(W1[i]);
}

// ==================== fp16 mma.sync GEMM ====================
// C[128x128 tile] = [drow ⊙](A @ Bt^T); A half [M][K] row-major, Bt half [N][K].
// AUX: Auxh[n][m] = rn(dcol[m] * C[m][n])  (transposed fp16, feeds next gemm).
// smem rows: 32 halves (64B) padded to 80B stride -> conflict-free LDS.32 frags.
#define ASTG 10240                 // bytes per stage (128 rows x 80B)
#define SMEM_MM (6 * ASTG)         // 3 stages A + 3 stages B = 61440B

__global__ __launch_bounds__(256) void k_hmma(const __half* __restrict__ Ah,
                                              const __half* __restrict__ Bh,
                                              float* __restrict__ C,
                                              __half* __restrict__ Aux,
                                              int K, int SCALE, int AUX) {
    extern __shared__ char smc[];
    char* As = smc;
    char* Bs = smc + 3 * ASTG;

    const int tid = threadIdx.x;
    const int wid = tid >> 5, lane = tid & 31;
    const int g = lane >> 2, t = lane & 3;
    const int wm = (wid & 1) * 64;
    const int wn = (wid >> 1) * 32;
    const int bm = blockIdx.y * 128, bn = blockIdx.x * 128;

    float acc[4][4][4];
#pragma unroll
    for (int i = 0; i < 4; i++)
#pragma unroll
        for (int j = 0; j < 4; j++)
#pragma unroll
            for (int r = 0; r < 4; r++) acc[i][j][r] = 0.f;

    const __half* Ag = Ah + (size_t)bm * K;
    const __half* Bg = Bh + (size_t)bn * K;
    const int KT = K / 32;

#define LOADSTAGE(kt, s) do {                                                  \
    char* ad = As + (s) * ASTG;                                                \
    char* bd = Bs + (s) * ASTG;                                                \
    _Pragma("unroll")                                                          \
    for (int i = 0; i < 2; i++) {                                              \
        int ch = tid + i * 256;                                                \
        int r = ch >> 2, c = ch & 3;                                           \
        cp16(ad + r * 80 + c * 16, Ag + (size_t)r * K + (kt) * 32 + c * 8);    \
        cp16(bd + r * 80 + c * 16, Bg + (size_t)r * K + (kt) * 32 + c * 8);    \
    }                                                                          \
    asm volatile("cp.async.commit_group;\n");                                  \
} while (0)

    LOADSTAGE(0, 0);
    LOADSTAGE(1, 1);

    for (int kt = 0; kt < KT; kt++) {
        if (kt == KT - 1) asm volatile("cp.async.wait_group 0;\n");
        else              asm volatile("cp.async.wait_group 1;\n");
        __syncthreads();

        int buf = kt % 3;
        const char* as = As + buf * ASTG;
        const char* bs = Bs + buf * ASTG;

#pragma unroll
        for (int ks = 0; ks < 2; ks++) {
            unsigned af[4][4];
#pragma unroll
            for (int mt = 0; mt < 4; mt++) {
                const char* ab = as + (wm + mt * 16 + g) * 80 + ks * 32 + t * 4;
                af[mt][0] = *(const unsigned*)(ab);
                af[mt][1] = *(const unsigned*)(ab + 8 * 80);
                af[mt][2] = *(const unsigned*)(ab + 16);
                af[mt][3] = *(const unsigned*)(ab + 8 * 80 + 16);
            }
            unsigned bf[4][2];
#pragma unroll
            for (int nt = 0; nt < 4; nt++) {
                const char* bb = bs + (wn + nt * 8 + g) * 80 + ks * 32 + t * 4;
                bf[nt][0] = *(const unsigned*)(bb);
                bf[nt][1] = *(const unsigned*)(bb + 16);
            }
#pragma unroll
            for (int mt = 0; mt < 4; mt++)
#pragma unroll
                for (int nt = 0; nt < 4; nt++) {
                    asm volatile(
                        "mma.sync.aligned.m16n8k16.row.col.f32.f16.f16.f32 "
                        "{%0,%1,%2,%3}, {%4,%5,%6,%7}, {%8,%9}, {%0,%1,%2,%3};\n"
                        : "+f"(acc[mt][nt][0]), "+f"(acc[mt][nt][1]),
                          "+f"(acc[mt][nt][2]), "+f"(acc[mt][nt][3])
                        : "r"(af[mt][0]), "r"(af[mt][1]), "r"(af[mt][2]), "r"(af[mt][3]),
                          "r"(bf[nt][0]), "r"(bf[nt][1]));
                }
        }
        if (kt + 2 < KT) LOADSTAGE(kt + 2, (kt + 2) % 3);
    }

    // epilogue
#pragma unroll
    for (int mt = 0; mt < 4; mt++) {
        int r0 = bm + wm + mt * 16 + g;
        int r1 = r0 + 8;
        float s0 = SCALE ? g_drow[r0] : 1.f;
        float s1 = SCALE ? g_drow[r1] : 1.f;
        float d0 = g_dcol[r0], d1 = g_dcol[r1];
#pragma unroll
        for (int nt = 0; nt < 4; nt++) {
            int c = bn + wn + nt * 8 + 2 * t;
            float v0 = acc[mt][nt][0] * s0, v1 = acc[mt][nt][1] * s0;
            float v2 = acc[mt][nt][2] * s1, v3 = acc[mt][nt][3] * s1;
            *(float2*)(C + (size_t)r0 * NH + c) = make_float2(v0, v1);
            *(float2*)(C + (size_t)r1 * NH + c) = make_float2(v2, v3);
            if (AUX) {
                Aux[(size_t)(c + 0) * NN + r0] = __float2half_rn(d0 * v0);
                Aux[(size_t)(c + 1) * NN + r0] = __float2half_rn(d0 * v1);
                Aux[(size_t)(c + 0) * NN + r1] = __float2half_rn(d1 * v2);
                Aux[(size_t)(c + 1) * NN + r1] = __float2half_rn(d1 * v3);
            }
        }
    }
}

// ==================== fused hidden + output-gemm ====================
__global__ void k_hidden(const float* __restrict__ W2) {
    int row  = blockIdx.x * 8 + (threadIdx.x >> 5);
    int lane = threadIdx.x & 31;
    float g0 = 0.f, g1 = 0.f;
    const float* xw = g_XW1 + (size_t)row * NH;
    const float* t1 = g_T1 + (size_t)row * NH;
    const float* t2 = g_T2 + (size_t)row * NH;
#pragma unroll
    for (int j = lane; j < NH; j += 32) {
        float p = FALPHA * xw[j] + (FALPHA - 1.f) * t1[j] - t2[j];
        float h = fmaxf(p, 0.f);
        g0 = fmaf(h, __ldg(&W2[j * 2 + 0]), g0);
        g1 = fmaf(h, __ldg(&W2[j * 2 + 1]), g1);
    }
#pragma unroll
    for (int o = 16; o; o >>= 1) {
        g0 += __shfl_xor_sync(0xffffffffu, g0, o);
        g1 += __shfl_xor_sync(0xffffffffu, g1, o);
    }
    if (!lane) {
        g_G[row * 2 + 0] = g0;
        g_G[row * 2 + 1] = g1;
    }
}

// ==================== narrow DAD apply (N=2), fp16 adj ====================
__global__ void k_narrow(const float* __restrict__ Bsrc, float* __restrict__ Sdst) {
    extern __shared__ float2 sB[];
    int tid = threadIdx.x;
    for (int k = tid; k < NN; k += 256) {
        float sc = g_dcol[k];
        sB[k] = make_float2(sc * Bsrc[k * 2], sc * Bsrc[k * 2 + 1]);
    }
    __syncthreads();

    int row  = blockIdx.x * 8 + (tid >> 5);
    int lane = tid & 31;
    const uint4* a = (const uint4*)(g_adjh + (size_t)row * NN);
    float s0 = 0.f, s1 = 0.f;
#pragma unroll 4
    for (int it = lane; it < NN / 8; it += 32) {
        uint4 w = a[it];
        int k = it * 8;
        float2 f0 = __half22float2(*(__half2*)&w.x);
        float2 f1 = __half22float2(*(__half2*)&w.y);
        float2 f2 = __half22float2(*(__half2*)&w.z);
        float2 f3 = __half22float2(*(__half2*)&w.w);
        s0 += f0.x * sB[k + 0].x + f0.y * sB[k + 1].x
            + f1.x * sB[k + 2].x + f1.y * sB[k + 3].x
            + f2.x * sB[k + 4].x + f2.y * sB[k + 5].x
            + f3.x * sB[k + 6].x + f3.y * sB[k + 7].x;
        s1 += f0.x * sB[k + 0].y + f0.y * sB[k + 1].y
            + f1.x * sB[k + 2].y + f1.y * sB[k + 3].y
            + f2.x * sB[k + 4].y + f2.y * sB[k + 5].y
            + f3.x * sB[k + 6].y + f3.y * sB[k + 7].y;
    }
#pragma unroll
    for (int o = 16; o; o >>= 1) {
        s0 += __shfl_xor_sync(0xffffffffu, s0, o);
        s1 += __shfl_xor_sync(0xffffffffu, s1, o);
    }
    if (!lane) {
        float sc = g_drow[row];
        Sdst[row * 2 + 0] = sc * s0;
        Sdst[row * 2 + 1] = sc * s1;
    }
}

// ==================== final log-softmax ====================
__global__ void k_final(const float* __restrict__ b2, float* __restrict__ out) {
    int i = blockIdx.x * blockDim.x + threadIdx.x;
    if (i >= NN) return;
    float o0 = FALPHA * g_G[i * 2 + 0] + (FALPHA - 1.f) * g_S1[i * 2 + 0] - g_S2[i * 2 + 0] + b2[0];
    float o1 = FALPHA * g_G[i * 2 + 1] + (FALPHA - 1.f) * g_S1[i * 2 + 1] - g_S2[i * 2 + 1] + b2[1];
    float m = fmaxf(o0, o1);
    float lse = m + logf(expf(o0 - m) + expf(o1 - m));
    out[i * 2 + 0] = o0 - lse;
    out[i * 2 + 1] = o1 - lse;
}

// ==================== launch ====================
extern "C" void kernel_launch(void* const* d_in, const int* in_sizes, int n_in,
                              void* d_out, int out_size) {
    const float* x   = (const float*)d_in[0];
    const float* adj = (const float*)d_in[1];
    const float* W1  = (const float*)d_in[2];
    const float* W2  = (const float*)d_in[3];
    const float* b2  = (const float*)d_in[4];
    float* out = (float*)d_out;
    (void)in_sizes; (void)n_in; (void)out_size;

    __half *pAdjh, *pXh, *pW1h, *pBs1h, *pBs2h;
    float *pXW1, *pT1, *pT2, *pG, *pS1, *pS2;
    cudaGetSymbolAddress((void**)&pAdjh, g_adjh);
    cudaGetSymbolAddress((void**)&pXh, g_xh);
    cudaGetSymbolAddress((void**)&pW1h, g_W1h);
    cudaGetSymbolAddress((void**)&pBs1h, g_Bs1h);
    cudaGetSymbolAddress((void**)&pBs2h, g_Bs2h);
    cudaGetSymbolAddress((void**)&pXW1, g_XW1);
    cudaGetSymbolAddress((void**)&pT1, g_T1);
    cudaGetSymbolAddress((void**)&pT2, g_T2);
    cudaGetSymbolAddress((void**)&pG, g_G);
    cudaGetSymbolAddress((void**)&pS1, g_S1);
    cudaGetSymbolAddress((void**)&pS2, g_S2);

    cudaFuncSetAttribute(k_hmma, cudaFuncAttributeMaxDynamicSharedMemorySize, SMEM_MM);
    cudaFuncSetAttribute(k_narrow, cudaFuncAttributeMaxDynamicSharedMemorySize, 65536);

    // degrees + fp16 adj in ONE pass
    k_zero<<<NN / 256, 256>>>();
    k_prep<<<128, 256>>>(adj);
    k_finalize<<<NN / 256, 256>>>();

    // fp16 operands
    k_halfx<<<(NN * NF) / 256, 256>>>(x);
    k_halfW1<<<(NF * NH) / 256, 256>>>(W1);

    // XW1 = x @ W1 ; aux Bs1h = rn(dcol ⊙ XW1)^T
    k_hmma<<<dim3(2, 64), 256, SMEM_MM>>>(pXh, pW1h, pXW1, pBs1h, NF, 0, 1);

    // T1 = drow ⊙ (adj @ Bs1) ; aux Bs2h = rn(dcol ⊙ T1)^T
    k_hmma<<<dim3(2, 64), 256, SMEM_MM>>>(pAdjh, pBs1h, pT1, pBs2h, NN, 1, 1);

    // T2 = drow ⊙ (adj @ Bs2)
    k_hmma<<<dim3(2, 64), 256, SMEM_MM>>>(pAdjh, pBs2h, pT2, (__half*)0, NN, 1, 0);

    // H = relu(adj_f @ XW1), G = H @ W2
    k_hidden<<<NN / 8, 256>>>(W2);

    // S1 = DAD @ G ; S2 = DAD @ S1  (fp16 adj, fp32 accum)
    k_narrow<<<NN / 8, 256, 65536>>>(pG, pS1);
    k_narrow<<<NN / 8, 256, 65536>>>(pS1, pS2);

    k_final<<<NN / 256, 256>>>(b2, out);
}